// round 9
// baseline (speedup 1.0000x reference)
#include <cuda_runtime.h>
#include <math.h>

#define BB   4
#define SS   512
#define DD   1024
#define HH   16
#define HDIM 64
#define FF   4096
#define VV   32000
#define NT   (BB*SS)      // 2048 tokens
#define NLAYER 6

// ---------------- scratch (static device globals; no allocs allowed) -------
__device__ float g_x   [NT*DD];
__device__ float g_a   [NT*DD];
__device__ float g_c   [NT*DD];
__device__ float g_qkv [NT*3*DD];
__device__ float g_q   [NT*DD];
__device__ float g_ao  [NT*DD];
__device__ float g_t   [NT*DD];
__device__ float g_h1  [NT*FF];
__device__ float g_eK  [NT*DD];
__device__ float g_eV  [NT*DD];
__device__ float g_wqkv[3*DD*DD];
__device__ float g_bqkv[3*DD];

// ---------------- embedding + sinusoidal posenc ----------------------------
__global__ __launch_bounds__(256)
void embed_kernel(const int* __restrict__ text, const float* __restrict__ We,
                  float* __restrict__ X)
{
    int n = blockIdx.x, t = threadIdx.x;
    int s = n & (SS - 1);
    int tok = text[n];
    int d = t * 4;
    float4 w = *(const float4*)(We + (size_t)tok * DD + d);
    const float cexp = -9.210340371976184f / (float)DD;   // -ln(10000)/D
    float div0 = expf((float)(d)     * cexp);
    float div1 = expf((float)(d + 2) * cexp);
    float4 o;
    o.x = w.x + sinf((float)s * div0);
    o.y = w.y + cosf((float)s * div0);
    o.z = w.z + sinf((float)s * div1);
    o.w = w.w + cosf((float)s * div1);
    *(float4*)(X + (size_t)n * DD + d) = o;
}

// ---------------- pack 3 weight matrices + biases into one ----------------
__global__ __launch_bounds__(256)
void pack3_kernel(const float* __restrict__ s0, const float* __restrict__ s1,
                  const float* __restrict__ s2, float* __restrict__ dst, int nEach4)
{
    int i = blockIdx.x * 256 + threadIdx.x;     // in float4 units
    if (i >= 3 * nEach4) return;
    const float* s = (i < nEach4) ? s0 : (i < 2 * nEach4) ? s1 : s2;
    int off = i - ((i < nEach4) ? 0 : (i < 2 * nEach4) ? nEach4 : 2 * nEach4);
    ((float4*)dst)[i] = ((const float4*)s)[off];
}

// ---------------- SGEMM v2: C[M,N] = A[M,K] @ W[N,K]^T (+bias)(+relu) ------
// 128x128 tile, BK=16, 256 threads, 8x8 micro-tile, double-buffered smem,
// register-staged global prefetch. EPI: 1 = +bias, 2 = +bias,relu.
template<int EPI>
__global__ __launch_bounds__(256, 2)
void sgemm_nt(const float* __restrict__ A, const float* __restrict__ W,
              const float* __restrict__ bias, float* __restrict__ C,
              int M, int N, int K)
{
    __shared__ __align__(16) float As[2][16][132];
    __shared__ __align__(16) float Bs[2][16][132];
    const int t  = threadIdx.x;
    const int tx = t & 15, ty = t >> 4;
    const int n0 = blockIdx.x * 128, m0 = blockIdx.y * 128;
    const int lr = t >> 1;            // row within tile (0..127)
    const int lk = (t & 1) * 8;       // k offset (0 or 8)
    const float* Ap = A + (size_t)(m0 + lr) * K + lk;
    const float* Wp = W + (size_t)(n0 + lr) * K + lk;

    float acc[8][8];
#pragma unroll
    for (int i = 0; i < 8; i++)
#pragma unroll
        for (int j = 0; j < 8; j++) acc[i][j] = 0.f;

    // preload tile 0
    float4 pa0 = *(const float4*)(Ap);
    float4 pa1 = *(const float4*)(Ap + 4);
    float4 pb0 = *(const float4*)(Wp);
    float4 pb1 = *(const float4*)(Wp + 4);
    {
        As[0][lk + 0][lr] = pa0.x; As[0][lk + 1][lr] = pa0.y;
        As[0][lk + 2][lr] = pa0.z; As[0][lk + 3][lr] = pa0.w;
        As[0][lk + 4][lr] = pa1.x; As[0][lk + 5][lr] = pa1.y;
        As[0][lk + 6][lr] = pa1.z; As[0][lk + 7][lr] = pa1.w;
        Bs[0][lk + 0][lr] = pb0.x; Bs[0][lk + 1][lr] = pb0.y;
        Bs[0][lk + 2][lr] = pb0.z; Bs[0][lk + 3][lr] = pb0.w;
        Bs[0][lk + 4][lr] = pb1.x; Bs[0][lk + 5][lr] = pb1.y;
        Bs[0][lk + 6][lr] = pb1.z; Bs[0][lk + 7][lr] = pb1.w;
    }
    __syncthreads();

    const int nkt = K >> 4;
    for (int kt = 0; kt < nkt; kt++) {
        const int cur = kt & 1;
        const int nxt = cur ^ 1;
        const bool has = (kt + 1 < nkt);
        if (has) {
            const float* Ap2 = Ap + (kt + 1) * 16;
            const float* Wp2 = Wp + (kt + 1) * 16;
            pa0 = *(const float4*)(Ap2);
            pa1 = *(const float4*)(Ap2 + 4);
            pb0 = *(const float4*)(Wp2);
            pb1 = *(const float4*)(Wp2 + 4);
        }
#pragma unroll
        for (int kk = 0; kk < 16; kk++) {
            float4 a0 = *(const float4*)(&As[cur][kk][ty * 4]);
            float4 a1 = *(const float4*)(&As[cur][kk][64 + ty * 4]);
            float4 b0 = *(const float4*)(&Bs[cur][kk][tx * 4]);
            float4 b1 = *(const float4*)(&Bs[cur][kk][64 + tx * 4]);
            float av8[8] = {a0.x, a0.y, a0.z, a0.w, a1.x, a1.y, a1.z, a1.w};
            float bv8[8] = {b0.x, b0.y, b0.z, b0.w, b1.x, b1.y, b1.z, b1.w};
#pragma unroll
            for (int i = 0; i < 8; i++)
#pragma unroll
                for (int j = 0; j < 8; j++)
                    acc[i][j] += av8[i] * bv8[j];
        }
        if (has) {
            As[nxt][lk + 0][lr] = pa0.x; As[nxt][lk + 1][lr] = pa0.y;
            As[nxt][lk + 2][lr] = pa0.z; As[nxt][lk + 3][lr] = pa0.w;
            As[nxt][lk + 4][lr] = pa1.x; As[nxt][lk + 5][lr] = pa1.y;
            As[nxt][lk + 6][lr] = pa1.z; As[nxt][lk + 7][lr] = pa1.w;
            Bs[nxt][lk + 0][lr] = pb0.x; Bs[nxt][lk + 1][lr] = pb0.y;
            Bs[nxt][lk + 2][lr] = pb0.z; Bs[nxt][lk + 3][lr] = pb0.w;
            Bs[nxt][lk + 4][lr] = pb1.x; Bs[nxt][lk + 5][lr] = pb1.y;
            Bs[nxt][lk + 6][lr] = pb1.z; Bs[nxt][lk + 7][lr] = pb1.w;
        }
        __syncthreads();
    }

#pragma unroll
    for (int i = 0; i < 8; i++) {
        int r = (i < 4) ? (ty * 4 + i) : (64 + ty * 4 + (i - 4));
        float* Cp = C + (size_t)(m0 + r) * N + n0;
#pragma unroll
        for (int jj = 0; jj < 2; jj++) {
            int cb = jj * 64 + tx * 4;
            float4 ov;
            float vs[4];
#pragma unroll
            for (int u = 0; u < 4; u++) {
                float vv = acc[i][jj * 4 + u];
                if (EPI >= 1) vv += bias[n0 + cb + u];
                if (EPI == 2) vv = fmaxf(vv, 0.f);
                vs[u] = vv;
            }
            ov.x = vs[0]; ov.y = vs[1]; ov.z = vs[2]; ov.w = vs[3];
            *(float4*)(Cp + cb) = ov;
        }
    }
}

// ---------------- Flash-style attention, fp32 ------------------------------
// One block per (q-tile of 64, head, batch). 256 threads, 4x4 micro-tiles.
// Row strides for Q/K/V are parameters (so the fused QKV buffer works).
#define ATTN_SMEM_FLOATS (3*64*72 + 64*64 + 3*64)

__global__ __launch_bounds__(256)
void attn_kernel(const float* __restrict__ Q, int ldq,
                 const float* __restrict__ Kp, int ldk,
                 const float* __restrict__ Vp, int ldv,
                 float* __restrict__ O, int causal)
{
    extern __shared__ float sm[];
    float* Qs   = sm;                 // [d][q], stride 72
    float* Ks   = Qs + 64 * 72;       // [d][k], stride 72
    float* Ps   = Ks + 64 * 72;       // [k][q], stride 72
    float* Vs   = Ps + 64 * 72;       // [k][d], stride 64
    float* mrow = Vs + 64 * 64;
    float* lrow = mrow + 64;
    float* crow = lrow + 64;

    const int t  = threadIdx.x;
    const int tx = t & 15, ty = t >> 4;
    const int qt = blockIdx.x, h = blockIdx.y, b = blockIdx.z;
    const size_t hq = (size_t)b * SS * ldq + (size_t)h * HDIM;
    const size_t hk = (size_t)b * SS * ldk + (size_t)h * HDIM;
    const size_t hv = (size_t)b * SS * ldv + (size_t)h * HDIM;
    const size_t ho = (size_t)b * SS * DD  + (size_t)h * HDIM;

    for (int idx = t; idx < 64 * 16; idx += 256) {
        int r = idx >> 4, d4 = (idx & 15) * 4;
        float4 qv = *(const float4*)(Q + hq + (size_t)(qt * 64 + r) * ldq + d4);
        Qs[(d4 + 0) * 72 + r] = qv.x;
        Qs[(d4 + 1) * 72 + r] = qv.y;
        Qs[(d4 + 2) * 72 + r] = qv.z;
        Qs[(d4 + 3) * 72 + r] = qv.w;
    }
    if (t < 64) { mrow[t] = -INFINITY; lrow[t] = 0.f; }
    float acc[4][4];
#pragma unroll
    for (int i = 0; i < 4; i++)
#pragma unroll
        for (int j = 0; j < 4; j++) acc[i][j] = 0.f;
    __syncthreads();

    const int nkt = causal ? (qt + 1) : (SS / 64);
    for (int kt = 0; kt < nkt; kt++) {
        for (int idx = t; idx < 64 * 16; idx += 256) {
            int r = idx >> 4, d4 = (idx & 15) * 4;
            float4 kv = *(const float4*)(Kp + hk + (size_t)(kt * 64 + r) * ldk + d4);
            Ks[(d4 + 0) * 72 + r] = kv.x;
            Ks[(d4 + 1) * 72 + r] = kv.y;
            Ks[(d4 + 2) * 72 + r] = kv.z;
            Ks[(d4 + 3) * 72 + r] = kv.w;
            float4 vv = *(const float4*)(Vp + hv + (size_t)(kt * 64 + r) * ldv + d4);
            *(float4*)(Vs + r * 64 + d4) = vv;
        }
        __syncthreads();

        // S = Q K^T
        float sc[4][4];
#pragma unroll
        for (int i = 0; i < 4; i++)
#pragma unroll
            for (int j = 0; j < 4; j++) sc[i][j] = 0.f;
#pragma unroll 8
        for (int dd = 0; dd < 64; dd++) {
            float4 a0 = *(const float4*)(Qs + dd * 72 + ty * 4);
            float4 b0 = *(const float4*)(Ks + dd * 72 + tx * 4);
            float av[4] = {a0.x, a0.y, a0.z, a0.w};
            float bv[4] = {b0.x, b0.y, b0.z, b0.w};
#pragma unroll
            for (int i = 0; i < 4; i++)
#pragma unroll
                for (int j = 0; j < 4; j++)
                    sc[i][j] += av[i] * bv[j];
        }
#pragma unroll
        for (int j = 0; j < 4; j++)
#pragma unroll
            for (int i = 0; i < 4; i++) {
                float val = sc[i][j] * 0.125f;
                if (causal && kt == qt && (tx * 4 + j) > (ty * 4 + i))
                    val = -INFINITY;
                Ps[(tx * 4 + j) * 72 + (ty * 4 + i)] = val;
            }
        __syncthreads();

        // online softmax: 4 threads per query row (bank-conflict-free)
        {
            const int r = t >> 2, sub = t & 3;
            float mt = -INFINITY;
            for (int kk = sub; kk < 64; kk += 4)
                mt = fmaxf(mt, Ps[kk * 72 + r]);
#pragma unroll
            for (int o = 1; o < 4; o <<= 1)
                mt = fmaxf(mt, __shfl_xor_sync(0xffffffffu, mt, o));
            float mn = fmaxf(mrow[r], mt);
            float sum = 0.f;
            for (int kk = sub; kk < 64; kk += 4) {
                float p = __expf(Ps[kk * 72 + r] - mn);
                Ps[kk * 72 + r] = p;
                sum += p;
            }
#pragma unroll
            for (int o = 1; o < 4; o <<= 1)
                sum += __shfl_xor_sync(0xffffffffu, sum, o);
            if (sub == 0) {
                float cr = __expf(mrow[r] - mn);
                lrow[r] = lrow[r] * cr + sum;
                mrow[r] = mn;
                crow[r] = cr;
            }
        }
        __syncthreads();

        // O = O*corr + P V
        float cr4[4];
#pragma unroll
        for (int i = 0; i < 4; i++) cr4[i] = crow[ty * 4 + i];
#pragma unroll
        for (int i = 0; i < 4; i++)
#pragma unroll
            for (int j = 0; j < 4; j++) acc[i][j] *= cr4[i];
#pragma unroll 8
        for (int kk = 0; kk < 64; kk++) {
            float4 a0 = *(const float4*)(Ps + kk * 72 + ty * 4);
            float4 b0 = *(const float4*)(Vs + kk * 64 + tx * 4);
            float av[4] = {a0.x, a0.y, a0.z, a0.w};
            float bv[4] = {b0.x, b0.y, b0.z, b0.w};
#pragma unroll
            for (int i = 0; i < 4; i++)
#pragma unroll
                for (int j = 0; j < 4; j++)
                    acc[i][j] += av[i] * bv[j];
        }
        __syncthreads();
    }

#pragma unroll
    for (int i = 0; i < 4; i++) {
        float inv = 1.f / lrow[ty * 4 + i];
        float4 ov;
        ov.x = acc[i][0] * inv; ov.y = acc[i][1] * inv;
        ov.z = acc[i][2] * inv; ov.w = acc[i][3] * inv;
        *(float4*)(O + ho + (size_t)(qt * 64 + ty * 4 + i) * DD + tx * 4) = ov;
    }
}

// ---------------- LayerNorm(a + b) * g + beta ------------------------------
__global__ __launch_bounds__(256)
void ln_kernel(const float* __restrict__ X, const float* __restrict__ Y,
               const float* __restrict__ gg, const float* __restrict__ be,
               float* __restrict__ out)
{
    __shared__ float red[34];
    const int row = blockIdx.x, t = threadIdx.x;
    const size_t base = (size_t)row * DD;
    float4 xv = *(const float4*)(X + base + t * 4);
    float4 yv = *(const float4*)(Y + base + t * 4);
    float v0 = xv.x + yv.x, v1 = xv.y + yv.y, v2 = xv.z + yv.z, v3 = xv.w + yv.w;

    float s = v0 + v1 + v2 + v3;
#pragma unroll
    for (int o = 16; o > 0; o >>= 1) s += __shfl_xor_sync(0xffffffffu, s, o);
    if ((t & 31) == 0) red[t >> 5] = s;
    __syncthreads();
    if (t == 0) {
        float tt = 0.f;
        for (int w = 0; w < 8; w++) tt += red[w];
        red[32] = tt * (1.f / (float)DD);
    }
    __syncthreads();
    float mu = red[32];

    float d0 = v0 - mu, d1 = v1 - mu, d2 = v2 - mu, d3 = v3 - mu;
    float s2 = d0 * d0 + d1 * d1 + d2 * d2 + d3 * d3;
#pragma unroll
    for (int o = 16; o > 0; o >>= 1) s2 += __shfl_xor_sync(0xffffffffu, s2, o);
    if ((t & 31) == 0) red[8 + (t >> 5)] = s2;
    __syncthreads();
    if (t == 0) {
        float tt = 0.f;
        for (int w = 0; w < 8; w++) tt += red[8 + w];
        red[33] = rsqrtf(tt * (1.f / (float)DD) + 1e-5f);
    }
    __syncthreads();
    float inv = red[33];

    int d = t * 4;
    float4 go = *(const float4*)(gg + d);
    float4 bo = *(const float4*)(be + d);
    float4 ov;
    ov.x = d0 * inv * go.x + bo.x;
    ov.y = d1 * inv * go.y + bo.y;
    ov.z = d2 * inv * go.z + bo.z;
    ov.w = d3 * inv * go.w + bo.w;
    *(float4*)(out + base + d) = ov;
}

// ---------------- softmax over batch axis (axis 0), in place ---------------
__global__ __launch_bounds__(256)
void softmax_b_kernel(float* __restrict__ out)
{
    const int idx = blockIdx.x * 256 + threadIdx.x;   // over S*V = 16,384,000
    const int stride = SS * VV;
    float l0 = out[idx];
    float l1 = out[idx + stride];
    float l2 = out[idx + 2 * stride];
    float l3 = out[idx + 3 * stride];
    float m  = fmaxf(fmaxf(l0, l1), fmaxf(l2, l3));
    float e0 = expf(l0 - m), e1 = expf(l1 - m), e2 = expf(l2 - m), e3 = expf(l3 - m);
    float inv = 1.f / (e0 + e1 + e2 + e3);
    out[idx]              = e0 * inv;
    out[idx + stride]     = e1 * inv;
    out[idx + 2 * stride] = e2 * inv;
    out[idx + 3 * stride] = e3 * inv;
}

// ---------------- host orchestration ---------------------------------------
extern "C" void kernel_launch(void* const* d_in, const int* in_sizes, int n_in,
                              void* d_out, int out_size)
{
    const int*   text = (const int*)  d_in[0];
    const float* enc  = (const float*)d_in[1];
    const float* We   = (const float*)d_in[2];
    const float* bout = (const float*)d_in[3];
    const float* lng  = (const float*)d_in[4];
    const float* lnb  = (const float*)d_in[5];
    const float* W1   = (const float*)d_in[6];
    const float* b1   = (const float*)d_in[7];
    const float* W2   = (const float*)d_in[8];
    const float* b2   = (const float*)d_in[9];
    const float* mWq  = (const float*)d_in[10]; const float* mbq = (const float*)d_in[11];
    const float* mWk  = (const float*)d_in[12]; const float* mbk = (const float*)d_in[13];
    const float* mWv  = (const float*)d_in[14]; const float* mbv = (const float*)d_in[15];
    const float* mWo  = (const float*)d_in[16]; const float* mbo = (const float*)d_in[17];
    const float* cWq  = (const float*)d_in[18]; const float* cbq = (const float*)d_in[19];
    const float* cWk  = (const float*)d_in[20]; const float* cbk = (const float*)d_in[21];
    const float* cWv  = (const float*)d_in[22]; const float* cbv = (const float*)d_in[23];
    const float* cWo  = (const float*)d_in[24]; const float* cbo = (const float*)d_in[25];
    float* out = (float*)d_out;

    float *x, *a, *c, *qkv, *q, *ao, *tb, *h1, *eK, *eV, *wqkv, *bqkv;
    cudaGetSymbolAddress((void**)&x,   g_x);
    cudaGetSymbolAddress((void**)&a,   g_a);
    cudaGetSymbolAddress((void**)&c,   g_c);
    cudaGetSymbolAddress((void**)&qkv, g_qkv);
    cudaGetSymbolAddress((void**)&q,   g_q);
    cudaGetSymbolAddress((void**)&ao,  g_ao);
    cudaGetSymbolAddress((void**)&tb,  g_t);
    cudaGetSymbolAddress((void**)&h1,  g_h1);
    cudaGetSymbolAddress((void**)&eK,  g_eK);
    cudaGetSymbolAddress((void**)&eV,  g_eV);
    cudaGetSymbolAddress((void**)&wqkv, g_wqkv);
    cudaGetSymbolAddress((void**)&bqkv, g_bqkv);

    const int ATTN_SMEM = ATTN_SMEM_FLOATS * 4;
    cudaFuncSetAttribute(attn_kernel,
                         cudaFuncAttributeMaxDynamicSharedMemorySize, ATTN_SMEM);

    dim3 gD (DD / 128, NT / 128);        // (8, 16)
    dim3 g3D(3 * DD / 128, NT / 128);    // (24, 16)
    dim3 gF (FF / 128, NT / 128);        // (32, 16)
    dim3 gV (VV / 128, NT / 128);        // (250, 16)
    dim3 gAt(SS / 64, HH, BB);           // (8, 16, 4)

    // embed + posenc
    embed_kernel<<<NT, 256>>>(text, We, x);

    // pack fused QKV weights/biases (once per launch; ~12MB)
    pack3_kernel<<<(3 * DD * DD / 4 + 255) / 256, 256>>>(mWq, mWk, mWv, wqkv, DD * DD / 4);
    pack3_kernel<<<(3 * DD / 4 + 255) / 256, 256>>>(mbq, mbk, mbv, bqkv, DD / 4);

    // encoder K/V are the same for every layer -> compute once
    sgemm_nt<1><<<gD, 256>>>(enc, cWk, cbk, eK, NT, DD, DD);
    sgemm_nt<1><<<gD, 256>>>(enc, cWv, cbv, eV, NT, DD, DD);

    for (int l = 0; l < NLAYER; l++) {
        // --- masked self-attention (fused QKV projection) ---
        sgemm_nt<1><<<g3D, 256>>>(x, wqkv, bqkv, qkv, NT, 3 * DD, DD);
        attn_kernel<<<gAt, 256, ATTN_SMEM>>>(qkv, 3 * DD,
                                             qkv + DD, 3 * DD,
                                             qkv + 2 * DD, 3 * DD, ao, 1);
        sgemm_nt<1><<<gD, 256>>>(ao, mWo, mbo, tb, NT, DD, DD);
        ln_kernel<<<NT, 256>>>(x, tb, lng, lnb, a);

        // --- cross-attention ---
        sgemm_nt<1><<<gD, 256>>>(a, cWq, cbq, q, NT, DD, DD);
        attn_kernel<<<gAt, 256, ATTN_SMEM>>>(q, DD, eK, DD, eV, DD, ao, 0);
        sgemm_nt<1><<<gD, 256>>>(ao, cWo, cbo, tb, NT, DD, DD);
        ln_kernel<<<NT, 256>>>(a, tb, lng, lnb, c);

        // --- FFN ---
        sgemm_nt<2><<<gF, 256>>>(c,  W1, b1, h1, NT, FF, DD);
        sgemm_nt<1><<<gD, 256>>>(h1, W2, b2, tb, NT, DD, FF);
        ln_kernel<<<NT, 256>>>(c, tb, lng, lnb, x);
    }

    // logits straight into d_out, then in-place softmax over batch axis
    sgemm_nt<1><<<gV, 256>>>(x, We, bout, out, NT, VV, DD);
    softmax_b_kernel<<<(SS * VV) / 256, 256>>>(out);
}

// round 10
// speedup vs baseline: 1.0017x; 1.0017x over previous
#include <cuda_runtime.h>
#include <math.h>

#define BB   4
#define SS   512
#define DD   1024
#define HH   16
#define HDIM 64
#define FF   4096
#define VV   32000
#define NT   (BB*SS)      // 2048 tokens
#define NLAYER 6

// ---------------- scratch (static device globals; no allocs allowed) -------
__device__ float g_x   [NT*DD];
__device__ float g_a   [NT*DD];
__device__ float g_c   [NT*DD];
__device__ float g_qkv [NT*3*DD];
__device__ float g_q   [NT*DD];
__device__ float g_ao  [NT*DD];
__device__ float g_t   [NT*DD];
__device__ float g_h1  [NT*FF];
__device__ float g_eK  [NT*DD];
__device__ float g_eV  [NT*DD];
__device__ float g_wqkv[3*DD*DD];
__device__ float g_bqkv[3*DD];

// ---------------- embedding + sinusoidal posenc ----------------------------
__global__ __launch_bounds__(256)
void embed_kernel(const int* __restrict__ text, const float* __restrict__ We,
                  float* __restrict__ X)
{
    int n = blockIdx.x, t = threadIdx.x;
    int s = n & (SS - 1);
    int tok = text[n];
    int d = t * 4;
    float4 w = *(const float4*)(We + (size_t)tok * DD + d);
    const float cexp = -9.210340371976184f / (float)DD;   // -ln(10000)/D
    float div0 = expf((float)(d)     * cexp);
    float div1 = expf((float)(d + 2) * cexp);
    float4 o;
    o.x = w.x + sinf((float)s * div0);
    o.y = w.y + cosf((float)s * div0);
    o.z = w.z + sinf((float)s * div1);
    o.w = w.w + cosf((float)s * div1);
    *(float4*)(X + (size_t)n * DD + d) = o;
}

// ---------------- pack 3 weight matrices + biases into one ----------------
__global__ __launch_bounds__(256)
void pack3_kernel(const float* __restrict__ s0, const float* __restrict__ s1,
                  const float* __restrict__ s2, float* __restrict__ dst, int nEach4)
{
    int i = blockIdx.x * 256 + threadIdx.x;     // in float4 units
    if (i >= 3 * nEach4) return;
    const float* s = (i < nEach4) ? s0 : (i < 2 * nEach4) ? s1 : s2;
    int off = i - ((i < nEach4) ? 0 : (i < 2 * nEach4) ? nEach4 : 2 * nEach4);
    ((float4*)dst)[i] = ((const float4*)s)[off];
}

// ---------------- SGEMM v2: C[M,N] = A[M,K] @ W[N,K]^T (+bias)(+relu) ------
// 128x128 tile, BK=16, 256 threads, 8x8 micro-tile, double-buffered smem,
// register-staged global prefetch. EPI: 1 = +bias, 2 = +bias,relu.
template<int EPI>
__global__ __launch_bounds__(256, 2)
void sgemm_nt(const float* __restrict__ A, const float* __restrict__ W,
              const float* __restrict__ bias, float* __restrict__ C,
              int M, int N, int K)
{
    __shared__ __align__(16) float As[2][16][132];
    __shared__ __align__(16) float Bs[2][16][132];
    const int t  = threadIdx.x;
    const int tx = t & 15, ty = t >> 4;
    const int n0 = blockIdx.x * 128, m0 = blockIdx.y * 128;
    const int lr = t >> 1;            // row within tile (0..127)
    const int lk = (t & 1) * 8;       // k offset (0 or 8)
    const float* Ap = A + (size_t)(m0 + lr) * K + lk;
    const float* Wp = W + (size_t)(n0 + lr) * K + lk;

    float acc[8][8];
#pragma unroll
    for (int i = 0; i < 8; i++)
#pragma unroll
        for (int j = 0; j < 8; j++) acc[i][j] = 0.f;

    // preload tile 0
    float4 pa0 = *(const float4*)(Ap);
    float4 pa1 = *(const float4*)(Ap + 4);
    float4 pb0 = *(const float4*)(Wp);
    float4 pb1 = *(const float4*)(Wp + 4);
    {
        As[0][lk + 0][lr] = pa0.x; As[0][lk + 1][lr] = pa0.y;
        As[0][lk + 2][lr] = pa0.z; As[0][lk + 3][lr] = pa0.w;
        As[0][lk + 4][lr] = pa1.x; As[0][lk + 5][lr] = pa1.y;
        As[0][lk + 6][lr] = pa1.z; As[0][lk + 7][lr] = pa1.w;
        Bs[0][lk + 0][lr] = pb0.x; Bs[0][lk + 1][lr] = pb0.y;
        Bs[0][lk + 2][lr] = pb0.z; Bs[0][lk + 3][lr] = pb0.w;
        Bs[0][lk + 4][lr] = pb1.x; Bs[0][lk + 5][lr] = pb1.y;
        Bs[0][lk + 6][lr] = pb1.z; Bs[0][lk + 7][lr] = pb1.w;
    }
    __syncthreads();

    const int nkt = K >> 4;
    for (int kt = 0; kt < nkt; kt++) {
        const int cur = kt & 1;
        const int nxt = cur ^ 1;
        const bool has = (kt + 1 < nkt);
        if (has) {
            const float* Ap2 = Ap + (kt + 1) * 16;
            const float* Wp2 = Wp + (kt + 1) * 16;
            pa0 = *(const float4*)(Ap2);
            pa1 = *(const float4*)(Ap2 + 4);
            pb0 = *(const float4*)(Wp2);
            pb1 = *(const float4*)(Wp2 + 4);
        }
#pragma unroll
        for (int kk = 0; kk < 16; kk++) {
            float4 a0 = *(const float4*)(&As[cur][kk][ty * 4]);
            float4 a1 = *(const float4*)(&As[cur][kk][64 + ty * 4]);
            float4 b0 = *(const float4*)(&Bs[cur][kk][tx * 4]);
            float4 b1 = *(const float4*)(&Bs[cur][kk][64 + tx * 4]);
            float av8[8] = {a0.x, a0.y, a0.z, a0.w, a1.x, a1.y, a1.z, a1.w};
            float bv8[8] = {b0.x, b0.y, b0.z, b0.w, b1.x, b1.y, b1.z, b1.w};
#pragma unroll
            for (int i = 0; i < 8; i++)
#pragma unroll
                for (int j = 0; j < 8; j++)
                    acc[i][j] += av8[i] * bv8[j];
        }
        if (has) {
            As[nxt][lk + 0][lr] = pa0.x; As[nxt][lk + 1][lr] = pa0.y;
            As[nxt][lk + 2][lr] = pa0.z; As[nxt][lk + 3][lr] = pa0.w;
            As[nxt][lk + 4][lr] = pa1.x; As[nxt][lk + 5][lr] = pa1.y;
            As[nxt][lk + 6][lr] = pa1.z; As[nxt][lk + 7][lr] = pa1.w;
            Bs[nxt][lk + 0][lr] = pb0.x; Bs[nxt][lk + 1][lr] = pb0.y;
            Bs[nxt][lk + 2][lr] = pb0.z; Bs[nxt][lk + 3][lr] = pb0.w;
            Bs[nxt][lk + 4][lr] = pb1.x; Bs[nxt][lk + 5][lr] = pb1.y;
            Bs[nxt][lk + 6][lr] = pb1.z; Bs[nxt][lk + 7][lr] = pb1.w;
        }
        __syncthreads();
    }

#pragma unroll
    for (int i = 0; i < 8; i++) {
        int r = (i < 4) ? (ty * 4 + i) : (64 + ty * 4 + (i - 4));
        float* Cp = C + (size_t)(m0 + r) * N + n0;
#pragma unroll
        for (int jj = 0; jj < 2; jj++) {
            int cb = jj * 64 + tx * 4;
            float4 ov;
            float vs[4];
#pragma unroll
            for (int u = 0; u < 4; u++) {
                float vv = acc[i][jj * 4 + u];
                if (EPI >= 1) vv += bias[n0 + cb + u];
                if (EPI == 2) vv = fmaxf(vv, 0.f);
                vs[u] = vv;
            }
            ov.x = vs[0]; ov.y = vs[1]; ov.z = vs[2]; ov.w = vs[3];
            *(float4*)(Cp + cb) = ov;
        }
    }
}

// ---------------- Flash-style attention, fp32 ------------------------------
// One block per (q-tile of 64, head, batch). 256 threads, 4x4 micro-tiles.
// Row strides for Q/K/V are parameters (so the fused QKV buffer works).
#define ATTN_SMEM_FLOATS (3*64*72 + 64*64 + 3*64)

__global__ __launch_bounds__(256)
void attn_kernel(const float* __restrict__ Q, int ldq,
                 const float* __restrict__ Kp, int ldk,
                 const float* __restrict__ Vp, int ldv,
                 float* __restrict__ O, int causal)
{
    extern __shared__ float sm[];
    float* Qs   = sm;                 // [d][q], stride 72
    float* Ks   = Qs + 64 * 72;       // [d][k], stride 72
    float* Ps   = Ks + 64 * 72;       // [k][q], stride 72
    float* Vs   = Ps + 64 * 72;       // [k][d], stride 64
    float* mrow = Vs + 64 * 64;
    float* lrow = mrow + 64;
    float* crow = lrow + 64;

    const int t  = threadIdx.x;
    const int tx = t & 15, ty = t >> 4;
    const int qt = blockIdx.x, h = blockIdx.y, b = blockIdx.z;
    const size_t hq = (size_t)b * SS * ldq + (size_t)h * HDIM;
    const size_t hk = (size_t)b * SS * ldk + (size_t)h * HDIM;
    const size_t hv = (size_t)b * SS * ldv + (size_t)h * HDIM;
    const size_t ho = (size_t)b * SS * DD  + (size_t)h * HDIM;

    for (int idx = t; idx < 64 * 16; idx += 256) {
        int r = idx >> 4, d4 = (idx & 15) * 4;
        float4 qv = *(const float4*)(Q + hq + (size_t)(qt * 64 + r) * ldq + d4);
        Qs[(d4 + 0) * 72 + r] = qv.x;
        Qs[(d4 + 1) * 72 + r] = qv.y;
        Qs[(d4 + 2) * 72 + r] = qv.z;
        Qs[(d4 + 3) * 72 + r] = qv.w;
    }
    if (t < 64) { mrow[t] = -INFINITY; lrow[t] = 0.f; }
    float acc[4][4];
#pragma unroll
    for (int i = 0; i < 4; i++)
#pragma unroll
        for (int j = 0; j < 4; j++) acc[i][j] = 0.f;
    __syncthreads();

    const int nkt = causal ? (qt + 1) : (SS / 64);
    for (int kt = 0; kt < nkt; kt++) {
        for (int idx = t; idx < 64 * 16; idx += 256) {
            int r = idx >> 4, d4 = (idx & 15) * 4;
            float4 kv = *(const float4*)(Kp + hk + (size_t)(kt * 64 + r) * ldk + d4);
            Ks[(d4 + 0) * 72 + r] = kv.x;
            Ks[(d4 + 1) * 72 + r] = kv.y;
            Ks[(d4 + 2) * 72 + r] = kv.z;
            Ks[(d4 + 3) * 72 + r] = kv.w;
            float4 vv = *(const float4*)(Vp + hv + (size_t)(kt * 64 + r) * ldv + d4);
            *(float4*)(Vs + r * 64 + d4) = vv;
        }
        __syncthreads();

        // S = Q K^T
        float sc[4][4];
#pragma unroll
        for (int i = 0; i < 4; i++)
#pragma unroll
            for (int j = 0; j < 4; j++) sc[i][j] = 0.f;
#pragma unroll 8
        for (int dd = 0; dd < 64; dd++) {
            float4 a0 = *(const float4*)(Qs + dd * 72 + ty * 4);
            float4 b0 = *(const float4*)(Ks + dd * 72 + tx * 4);
            float av[4] = {a0.x, a0.y, a0.z, a0.w};
            float bv[4] = {b0.x, b0.y, b0.z, b0.w};
#pragma unroll
            for (int i = 0; i < 4; i++)
#pragma unroll
                for (int j = 0; j < 4; j++)
                    sc[i][j] += av[i] * bv[j];
        }
#pragma unroll
        for (int j = 0; j < 4; j++)
#pragma unroll
            for (int i = 0; i < 4; i++) {
                float val = sc[i][j] * 0.125f;
                if (causal && kt == qt && (tx * 4 + j) > (ty * 4 + i))
                    val = -INFINITY;
                Ps[(tx * 4 + j) * 72 + (ty * 4 + i)] = val;
            }
        __syncthreads();

        // online softmax: 4 threads per query row (bank-conflict-free)
        {
            const int r = t >> 2, sub = t & 3;
            float mt = -INFINITY;
            for (int kk = sub; kk < 64; kk += 4)
                mt = fmaxf(mt, Ps[kk * 72 + r]);
#pragma unroll
            for (int o = 1; o < 4; o <<= 1)
                mt = fmaxf(mt, __shfl_xor_sync(0xffffffffu, mt, o));
            float mn = fmaxf(mrow[r], mt);
            float sum = 0.f;
            for (int kk = sub; kk < 64; kk += 4) {
                float p = __expf(Ps[kk * 72 + r] - mn);
                Ps[kk * 72 + r] = p;
                sum += p;
            }
#pragma unroll
            for (int o = 1; o < 4; o <<= 1)
                sum += __shfl_xor_sync(0xffffffffu, sum, o);
            if (sub == 0) {
                float cr = __expf(mrow[r] - mn);
                lrow[r] = lrow[r] * cr + sum;
                mrow[r] = mn;
                crow[r] = cr;
            }
        }
        __syncthreads();

        // O = O*corr + P V
        float cr4[4];
#pragma unroll
        for (int i = 0; i < 4; i++) cr4[i] = crow[ty * 4 + i];
#pragma unroll
        for (int i = 0; i < 4; i++)
#pragma unroll
            for (int j = 0; j < 4; j++) acc[i][j] *= cr4[i];
#pragma unroll 8
        for (int kk = 0; kk < 64; kk++) {
            float4 a0 = *(const float4*)(Ps + kk * 72 + ty * 4);
            float4 b0 = *(const float4*)(Vs + kk * 64 + tx * 4);
            float av[4] = {a0.x, a0.y, a0.z, a0.w};
            float bv[4] = {b0.x, b0.y, b0.z, b0.w};
#pragma unroll
            for (int i = 0; i < 4; i++)
#pragma unroll
                for (int j = 0; j < 4; j++)
                    acc[i][j] += av[i] * bv[j];
        }
        __syncthreads();
    }

#pragma unroll
    for (int i = 0; i < 4; i++) {
        float inv = 1.f / lrow[ty * 4 + i];
        float4 ov;
        ov.x = acc[i][0] * inv; ov.y = acc[i][1] * inv;
        ov.z = acc[i][2] * inv; ov.w = acc[i][3] * inv;
        *(float4*)(O + ho + (size_t)(qt * 64 + ty * 4 + i) * DD + tx * 4) = ov;
    }
}

// ---------------- LayerNorm(a + b) * g + beta ------------------------------
__global__ __launch_bounds__(256)
void ln_kernel(const float* __restrict__ X, const float* __restrict__ Y,
               const float* __restrict__ gg, const float* __restrict__ be,
               float* __restrict__ out)
{
    __shared__ float red[34];
    const int row = blockIdx.x, t = threadIdx.x;
    const size_t base = (size_t)row * DD;
    float4 xv = *(const float4*)(X + base + t * 4);
    float4 yv = *(const float4*)(Y + base + t * 4);
    float v0 = xv.x + yv.x, v1 = xv.y + yv.y, v2 = xv.z + yv.z, v3 = xv.w + yv.w;

    float s = v0 + v1 + v2 + v3;
#pragma unroll
    for (int o = 16; o > 0; o >>= 1) s += __shfl_xor_sync(0xffffffffu, s, o);
    if ((t & 31) == 0) red[t >> 5] = s;
    __syncthreads();
    if (t == 0) {
        float tt = 0.f;
        for (int w = 0; w < 8; w++) tt += red[w];
        red[32] = tt * (1.f / (float)DD);
    }
    __syncthreads();
    float mu = red[32];

    float d0 = v0 - mu, d1 = v1 - mu, d2 = v2 - mu, d3 = v3 - mu;
    float s2 = d0 * d0 + d1 * d1 + d2 * d2 + d3 * d3;
#pragma unroll
    for (int o = 16; o > 0; o >>= 1) s2 += __shfl_xor_sync(0xffffffffu, s2, o);
    if ((t & 31) == 0) red[8 + (t >> 5)] = s2;
    __syncthreads();
    if (t == 0) {
        float tt = 0.f;
        for (int w = 0; w < 8; w++) tt += red[8 + w];
        red[33] = rsqrtf(tt * (1.f / (float)DD) + 1e-5f);
    }
    __syncthreads();
    float inv = red[33];

    int d = t * 4;
    float4 go = *(const float4*)(gg + d);
    float4 bo = *(const float4*)(be + d);
    float4 ov;
    ov.x = d0 * inv * go.x + bo.x;
    ov.y = d1 * inv * go.y + bo.y;
    ov.z = d2 * inv * go.z + bo.z;
    ov.w = d3 * inv * go.w + bo.w;
    *(float4*)(out + base + d) = ov;
}

// ---------------- softmax over batch axis (axis 0), in place ---------------
__global__ __launch_bounds__(256)
void softmax_b_kernel(float* __restrict__ out)
{
    const int idx = blockIdx.x * 256 + threadIdx.x;   // over S*V = 16,384,000
    const int stride = SS * VV;
    float l0 = out[idx];
    float l1 = out[idx + stride];
    float l2 = out[idx + 2 * stride];
    float l3 = out[idx + 3 * stride];
    float m  = fmaxf(fmaxf(l0, l1), fmaxf(l2, l3));
    float e0 = expf(l0 - m), e1 = expf(l1 - m), e2 = expf(l2 - m), e3 = expf(l3 - m);
    float inv = 1.f / (e0 + e1 + e2 + e3);
    out[idx]              = e0 * inv;
    out[idx + stride]     = e1 * inv;
    out[idx + 2 * stride] = e2 * inv;
    out[idx + 3 * stride] = e3 * inv;
}

// ---------------- host orchestration ---------------------------------------
extern "C" void kernel_launch(void* const* d_in, const int* in_sizes, int n_in,
                              void* d_out, int out_size)
{
    const int*   text = (const int*)  d_in[0];
    const float* enc  = (const float*)d_in[1];
    const float* We   = (const float*)d_in[2];
    const float* bout = (const float*)d_in[3];
    const float* lng  = (const float*)d_in[4];
    const float* lnb  = (const float*)d_in[5];
    const float* W1   = (const float*)d_in[6];
    const float* b1   = (const float*)d_in[7];
    const float* W2   = (const float*)d_in[8];
    const float* b2   = (const float*)d_in[9];
    const float* mWq  = (const float*)d_in[10]; const float* mbq = (const float*)d_in[11];
    const float* mWk  = (const float*)d_in[12]; const float* mbk = (const float*)d_in[13];
    const float* mWv  = (const float*)d_in[14]; const float* mbv = (const float*)d_in[15];
    const float* mWo  = (const float*)d_in[16]; const float* mbo = (const float*)d_in[17];
    const float* cWq  = (const float*)d_in[18]; const float* cbq = (const float*)d_in[19];
    const float* cWk  = (const float*)d_in[20]; const float* cbk = (const float*)d_in[21];
    const float* cWv  = (const float*)d_in[22]; const float* cbv = (const float*)d_in[23];
    const float* cWo  = (const float*)d_in[24]; const float* cbo = (const float*)d_in[25];
    float* out = (float*)d_out;

    float *x, *a, *c, *qkv, *q, *ao, *tb, *h1, *eK, *eV, *wqkv, *bqkv;
    cudaGetSymbolAddress((void**)&x,   g_x);
    cudaGetSymbolAddress((void**)&a,   g_a);
    cudaGetSymbolAddress((void**)&c,   g_c);
    cudaGetSymbolAddress((void**)&qkv, g_qkv);
    cudaGetSymbolAddress((void**)&q,   g_q);
    cudaGetSymbolAddress((void**)&ao,  g_ao);
    cudaGetSymbolAddress((void**)&tb,  g_t);
    cudaGetSymbolAddress((void**)&h1,  g_h1);
    cudaGetSymbolAddress((void**)&eK,  g_eK);
    cudaGetSymbolAddress((void**)&eV,  g_eV);
    cudaGetSymbolAddress((void**)&wqkv, g_wqkv);
    cudaGetSymbolAddress((void**)&bqkv, g_bqkv);

    const int ATTN_SMEM = ATTN_SMEM_FLOATS * 4;
    cudaFuncSetAttribute(attn_kernel,
                         cudaFuncAttributeMaxDynamicSharedMemorySize, ATTN_SMEM);

    dim3 gD (DD / 128, NT / 128);        // (8, 16)
    dim3 g3D(3 * DD / 128, NT / 128);    // (24, 16)
    dim3 gF (FF / 128, NT / 128);        // (32, 16)
    dim3 gV (VV / 128, NT / 128);        // (250, 16)
    dim3 gAt(SS / 64, HH, BB);           // (8, 16, 4)

    // embed + posenc
    embed_kernel<<<NT, 256>>>(text, We, x);

    // pack fused QKV weights/biases (once per launch; ~12MB)
    pack3_kernel<<<(3 * DD * DD / 4 + 255) / 256, 256>>>(mWq, mWk, mWv, wqkv, DD * DD / 4);
    pack3_kernel<<<(3 * DD / 4 + 255) / 256, 256>>>(mbq, mbk, mbv, bqkv, DD / 4);

    // encoder K/V are the same for every layer -> compute once
    sgemm_nt<1><<<gD, 256>>>(enc, cWk, cbk, eK, NT, DD, DD);
    sgemm_nt<1><<<gD, 256>>>(enc, cWv, cbv, eV, NT, DD, DD);

    for (int l = 0; l < NLAYER; l++) {
        // --- masked self-attention (fused QKV projection) ---
        sgemm_nt<1><<<g3D, 256>>>(x, wqkv, bqkv, qkv, NT, 3 * DD, DD);
        attn_kernel<<<gAt, 256, ATTN_SMEM>>>(qkv, 3 * DD,
                                             qkv + DD, 3 * DD,
                                             qkv + 2 * DD, 3 * DD, ao, 1);
        sgemm_nt<1><<<gD, 256>>>(ao, mWo, mbo, tb, NT, DD, DD);
        ln_kernel<<<NT, 256>>>(x, tb, lng, lnb, a);

        // --- cross-attention ---
        sgemm_nt<1><<<gD, 256>>>(a, cWq, cbq, q, NT, DD, DD);
        attn_kernel<<<gAt, 256, ATTN_SMEM>>>(q, DD, eK, DD, eV, DD, ao, 0);
        sgemm_nt<1><<<gD, 256>>>(ao, cWo, cbo, tb, NT, DD, DD);
        ln_kernel<<<NT, 256>>>(a, tb, lng, lnb, c);

        // --- FFN ---
        sgemm_nt<2><<<gF, 256>>>(c,  W1, b1, h1, NT, FF, DD);
        sgemm_nt<1><<<gD, 256>>>(h1, W2, b2, tb, NT, DD, FF);
        ln_kernel<<<NT, 256>>>(c, tb, lng, lnb, x);
    }

    // logits straight into d_out, then in-place softmax over batch axis
    sgemm_nt<1><<<gV, 256>>>(x, We, bout, out, NT, VV, DD);
    softmax_b_kernel<<<(SS * VV) / 256, 256>>>(out);
}